// round 14
// baseline (speedup 1.0000x reference)
#include <cuda_runtime.h>
#include <cstdint>

// Problem constants
#define Bn 64
#define Sn 512
#define Nn 128
#define Dn 768
#define On 3

// Scratch (device globals -- no allocations allowed)
__device__ float g_x[(size_t)Bn * Nn * Dn];      // exact node features (ping)
__device__ float g_x2[(size_t)Bn * Nn * Dn];     // exact node features (pong)
__device__ float g_xr[(size_t)Bn * Nn * Dn];     // tf32-rounded, K-permuted (ping)
__device__ float g_xr2[(size_t)Bn * Nn * Dn];    // tf32-rounded, K-permuted (pong)
__device__ float g_t[(size_t)Bn * Nn * Dn];      // span sums, rounded+permuted [B*N, D]
__device__ float g_adj[(size_t)Bn * Nn * Nn];    // clamped adjacency, permuted cols (exact 0/1)
__device__ float g_denom[(size_t)Bn * Nn];       // row-degree + 1e-7
__device__ float g_tmax[(size_t)Bn * Dn];        // target max-pool
__device__ float g_Wt[4 * (size_t)Dn * Dn];      // W^T [N,K], rounded + K-permuted

// ===========================================================================
// helpers
// ===========================================================================
__device__ __forceinline__ uint32_t smem_u32(const void* p) {
    uint32_t a;
    asm("{ .reg .u64 t; cvta.to.shared.u64 t, %1; cvt.u32.u64 %0, t; }" : "=r"(a) : "l"(p));
    return a;
}
__device__ __forceinline__ float f2tf(float f) {
    uint32_t u;
    asm("cvt.rna.tf32.f32 %0, %1;" : "=r"(u) : "f"(f));
    return __uint_as_float(u);
}
// K-permutation within each 16-column group (involution)
__device__ __forceinline__ int permc(int c) {
    return (c & ~15) | ((c & 3) << 2) | ((c >> 2) & 3);
}
#define CP_ASYNC16(dst, src) \
    asm volatile("cp.async.cg.shared.global [%0], [%1], 16;" :: "r"(dst), "l"(src) : "memory")
#define CP_COMMIT() asm volatile("cp.async.commit_group;" ::: "memory")
#define CP_WAIT(n)  asm volatile("cp.async.wait_group %0;" :: "n"(n) : "memory")

__device__ __forceinline__ void mma_tf32(float& c0, float& c1, float& c2, float& c3,
                                         float a0, float a1, float a2, float a3,
                                         float b0, float b1) {
    asm volatile(
        "mma.sync.aligned.m16n8k8.row.col.f32.tf32.tf32.f32 "
        "{%0,%1,%2,%3}, {%4,%5,%6,%7}, {%8,%9}, {%0,%1,%2,%3};"
        : "+f"(c0), "+f"(c1), "+f"(c2), "+f"(c3)
        : "r"(__float_as_uint(a0)), "r"(__float_as_uint(a1)),
          "r"(__float_as_uint(a2)), "r"(__float_as_uint(a3)),
          "r"(__float_as_uint(b0)), "r"(__float_as_uint(b1)));
}

// ===========================================================================
// small prep kernels
// ===========================================================================
__global__ void adj_kernel(const float* __restrict__ dg, const float* __restrict__ dg1) {
    int row = blockIdx.x;
    int tid = threadIdx.x;
    float a = dg[(size_t)row * Nn + tid] + dg1[(size_t)row * Nn + tid];
    a = fminf(a, 1.0f);
    g_adj[(size_t)row * Nn + permc(tid)] = a;
    __shared__ float s[128];
    s[tid] = a;
    __syncthreads();
    #pragma unroll
    for (int st = 64; st > 0; st >>= 1) {
        if (tid < st) s[tid] += s[tid + st];
        __syncthreads();
    }
    if (tid == 0) g_denom[row] = s[0] + 1e-7f;
}

__global__ void span_kernel(const float* __restrict__ se, const int* __restrict__ tran) {
    int row = blockIdx.x;
    int b = row >> 7;
    int s0 = tran[row * 2] + 1;
    int e0 = tran[row * 2 + 1] + 1;
    for (int d = threadIdx.x; d < Dn; d += 256) {
        float acc = 0.0f;
        for (int s = s0; s < e0; ++s)
            acc += se[((size_t)b * Sn + s) * Dn + d];
        g_t[(size_t)row * Dn + permc(d)] = f2tf(acc);
    }
}

__global__ void tmax_kernel(const float* __restrict__ se, const int* __restrict__ tspan) {
    int b = blockIdx.x;
    int l = tspan[b * 2];
    int r = tspan[b * 2 + 1];
    for (int d = threadIdx.x; d < Dn; d += 256) {
        float m = -3.402823466e38f;
        for (int s = l; s < r; ++s)
            m = fmaxf(m, se[((size_t)b * Sn + s) * Dn + d]);
        g_tmax[(size_t)b * Dn + d] = m;
    }
}

// transpose + round + K-permute 4 weight matrices [K=768, N=768] -> g_Wt[w][N][Kperm]
__global__ void wtrans_kernel(const float* __restrict__ W0, const float* __restrict__ W1,
                              const float* __restrict__ W2, const float* __restrict__ W3) {
    __shared__ float t[32][33];
    int w = blockIdx.z;
    const float* W = (w == 0) ? W0 : (w == 1) ? W1 : (w == 2) ? W2 : W3;
    float* O = g_Wt + (size_t)w * Dn * Dn;
    int nx = blockIdx.x * 32;
    int ky = blockIdx.y * 32;
    int tx = threadIdx.x;
    for (int i = threadIdx.y; i < 32; i += 8)
        t[i][tx] = W[(size_t)(ky + i) * Dn + nx + tx];
    __syncthreads();
    for (int i = threadIdx.y; i < 32; i += 8)
        O[(size_t)(nx + i) * Dn + permc(ky + tx)] = f2tf(t[tx][i]);
}

// ===========================================================================
// shared tile geometry: 128(M) x 96(N), BK=16, 384 threads (12 warps of 32x32)
// 24 warps/SM at occ 2 (6/SMSP) for MMA latency hiding
// ===========================================================================
#define BK 16
#define TSTRIDE 16
#define BN 96
#define NTHR 384
#define TILE_A_F (128 * TSTRIDE)          // 2048 floats
#define TILE_B_F (BN * TSTRIDE)           // 1536 floats
#define STAGE_F (TILE_A_F + TILE_B_F)     // 3584 floats
#define NST 4
#define REGION0_F (NST * STAGE_F)         // 14336 floats (pipeline / P^T staging)
#define GEMM_SMEM_BYTES (REGION0_F * 4)   // 57344
#define FUSED_SMEM_BYTES ((REGION0_F + NST * TILE_A_F) * 4)  // 90112

// MMA body: warp tile 32x32 (av[2][2], bv[4]); kstep-outer ordering
#define MMA_TILE_BODY(as, bs)                                                          \
    do {                                                                               \
        float4 av[2][2], bv[4];                                                        \
        _Pragma("unroll")                                                              \
        for (int mi = 0; mi < 2; ++mi) {                                               \
            av[mi][0] = *(const float4*)&(as)[(wm + mi * 16 + lg) * TSTRIDE + 4 * tg]; \
            av[mi][1] = *(const float4*)&(as)[(wm + mi * 16 + lg + 8) * TSTRIDE + 4 * tg]; \
        }                                                                              \
        _Pragma("unroll")                                                              \
        for (int ni = 0; ni < 4; ++ni)                                                 \
            bv[ni] = *(const float4*)&(bs)[(wn + ni * 8 + lg) * TSTRIDE + 4 * tg];     \
        _Pragma("unroll")                                                              \
        for (int mi = 0; mi < 2; ++mi)                                                 \
            _Pragma("unroll")                                                          \
            for (int ni = 0; ni < 4; ++ni)                                             \
                mma_tf32(c[mi][ni][0], c[mi][ni][1], c[mi][ni][2], c[mi][ni][3],       \
                         av[mi][0].x, av[mi][1].x, av[mi][0].y, av[mi][1].y,           \
                         bv[ni].x, bv[ni].y);                                          \
        _Pragma("unroll")                                                              \
        for (int mi = 0; mi < 2; ++mi)                                                 \
            _Pragma("unroll")                                                          \
            for (int ni = 0; ni < 4; ++ni)                                             \
                mma_tf32(c[mi][ni][0], c[mi][ni][1], c[mi][ni][2], c[mi][ni][3],       \
                         av[mi][0].z, av[mi][1].z, av[mi][0].w, av[mi][1].w,           \
                         bv[ni].z, bv[ni].w);                                          \
    } while (0)

// loaders for 384-thread blocks
#define LOAD_A_TILE(sbase, ptr, ld, k0)                                                \
    do {                                                                               \
        int id = tid;                                                                  \
        CP_ASYNC16((sbase) + ((id >> 2) * TSTRIDE + (id & 3) * 4) * 4,                 \
                   (ptr) + (size_t)(id >> 2) * (ld) + (k0) + (id & 3) * 4);            \
        if (tid < 128) {                                                               \
            int id2 = tid + 384;                                                       \
            CP_ASYNC16((sbase) + ((id2 >> 2) * TSTRIDE + (id2 & 3) * 4) * 4,           \
                       (ptr) + (size_t)(id2 >> 2) * (ld) + (k0) + (id2 & 3) * 4);      \
        }                                                                              \
    } while (0)

#define LOAD_B_TILE(sbase, ptr, ld, k0)                                                \
    do {                                                                               \
        int id = tid;                                                                  \
        CP_ASYNC16((sbase) + ((id >> 2) * TSTRIDE + (id & 3) * 4) * 4,                 \
                   (ptr) + (size_t)(id >> 2) * (ld) + (k0) + (id & 3) * 4);            \
    } while (0)

// ===========================================================================
// projection GEMM: xo = relu(g_t @ Wproj^T); xro = rounded/permuted copy
// ===========================================================================
template <int KTILES>
__global__ void __launch_bounds__(NTHR, 2)
gemm_proj(const float* __restrict__ A, const float* __restrict__ B,
          float* __restrict__ Xout, float* __restrict__ XRout) {
    extern __shared__ float smem[];
    int tid = threadIdx.x;
    int lane = tid & 31;
    int warp = tid >> 5;          // 0..11
    int wm = (warp & 3) * 32;     // M row base (0/32/64/96)
    int wn = (warp >> 2) * 32;    // N col base (0/32/64)
    int lg = lane >> 2;
    int tg = lane & 3;

    const float* Ab = A + (size_t)blockIdx.y * 128 * Dn;
    const float* Bb = B + (size_t)blockIdx.x * BN * Dn;

    float c[2][4][4];
    #pragma unroll
    for (int i = 0; i < 2; ++i)
        #pragma unroll
        for (int j = 0; j < 4; ++j)
            #pragma unroll
            for (int k = 0; k < 4; ++k) c[i][j][k] = 0.0f;

    uint32_t sAbase[NST], sBbase[NST];
    #pragma unroll
    for (int s = 0; s < NST; ++s) {
        sAbase[s] = smem_u32(smem + s * STAGE_F);
        sBbase[s] = smem_u32(smem + s * STAGE_F + TILE_A_F);
    }

    auto load_stage = [&](int it, int buf) {
        int k0 = it * BK;
        LOAD_A_TILE(sAbase[buf], Ab, Dn, k0);
        LOAD_B_TILE(sBbase[buf], Bb, Dn, k0);
        CP_COMMIT();
    };

    load_stage(0, 0);
    load_stage(1, 1);
    load_stage(2, 2);
    for (int it = 0; it < KTILES; ++it) {
        int buf = it & (NST - 1);
        if (it == KTILES - 1) { CP_WAIT(0); } else { CP_WAIT(2); }
        __syncthreads();
        if (it + 3 < KTILES) load_stage(it + 3, (it + 3) & (NST - 1));

        const float* as = smem + buf * STAGE_F;
        const float* bs = smem + buf * STAGE_F + TILE_A_F;
        MMA_TILE_BODY(as, bs);
    }

    size_t row0 = (size_t)blockIdx.y * 128;
    #pragma unroll
    for (int mi = 0; mi < 2; ++mi) {
        int r = wm + mi * 16 + lg;
        #pragma unroll
        for (int ni = 0; ni < 4; ++ni) {
            int cc = blockIdx.x * BN + wn + ni * 8 + 2 * tg;
            float v0 = fmaxf(c[mi][ni][0], 0.0f);
            float v1 = fmaxf(c[mi][ni][1], 0.0f);
            float v2 = fmaxf(c[mi][ni][2], 0.0f);
            float v3 = fmaxf(c[mi][ni][3], 0.0f);
            Xout[(row0 + r) * Dn + cc]          = v0;
            Xout[(row0 + r) * Dn + cc + 1]      = v1;
            Xout[(row0 + r + 8) * Dn + cc]      = v2;
            Xout[(row0 + r + 8) * Dn + cc + 1]  = v3;
            XRout[(row0 + r) * Dn + permc(cc)]         = f2tf(v0);
            XRout[(row0 + r) * Dn + permc(cc + 1)]     = f2tf(v1);
            XRout[(row0 + r + 8) * Dn + permc(cc)]     = f2tf(v2);
            XRout[(row0 + r + 8) * Dn + permc(cc + 1)] = f2tf(v3);
        }
    }
}

// ===========================================================================
// FUSED GCN layer (ping-pong, race-free): per (dtile=blockIdx.x, b=blockIdx.y)
// ===========================================================================
template <int WXR>
__global__ void __launch_bounds__(NTHR, 2)
gcn_fused(const float* __restrict__ XRin, const float* __restrict__ Xin,
          float* __restrict__ Xout, float* __restrict__ XRout,
          const float* __restrict__ B, const float* __restrict__ bias) {
    extern __shared__ float smem[];
    int tid = threadIdx.x;
    int lane = tid & 31;
    int warp = tid >> 5;
    int wm = (warp & 3) * 32;
    int wn = (warp >> 2) * 32;
    int lg = lane >> 2;
    int tg = lane & 3;

    int b = blockIdx.y;
    const float* Ab = XRin + (size_t)b * 128 * Dn;
    const float* Bb = B + (size_t)blockIdx.x * BN * Dn;

    float c[2][4][4];
    #pragma unroll
    for (int i = 0; i < 2; ++i)
        #pragma unroll
        for (int j = 0; j < 4; ++j)
            #pragma unroll
            for (int k = 0; k < 4; ++k) c[i][j][k] = 0.0f;

    uint32_t sAbase[NST], sBbase[NST], sAdj[NST];
    #pragma unroll
    for (int s = 0; s < NST; ++s) {
        sAbase[s] = smem_u32(smem + s * STAGE_F);
        sBbase[s] = smem_u32(smem + s * STAGE_F + TILE_A_F);
        sAdj[s]   = smem_u32(smem + REGION0_F + s * TILE_A_F);
    }

    // ---- phase 1: P = XRin[b] @ W^T ----
    auto load_stage = [&](int it, int buf) {
        int k0 = it * BK;
        LOAD_A_TILE(sAbase[buf], Ab, Dn, k0);
        LOAD_B_TILE(sBbase[buf], Bb, Dn, k0);
        CP_COMMIT();
    };

    load_stage(0, 0);
    load_stage(1, 1);
    load_stage(2, 2);
    const int KT1 = Dn / BK;   // 48
    for (int it = 0; it < KT1; ++it) {
        int buf = it & (NST - 1);
        if (it == KT1 - 1) { CP_WAIT(0); } else { CP_WAIT(2); }
        __syncthreads();
        if (it + 3 < KT1) load_stage(it + 3, (it + 3) & (NST - 1));

        const float* as = smem + buf * STAGE_F;
        const float* bs = smem + buf * STAGE_F + TILE_A_F;
        MMA_TILE_BODY(as, bs);
    }
    __syncthreads();

    // ---- stage P^T into region0: 8 k-chunked tiles [96 d-rows][16 node-cols] ----
    #pragma unroll
    for (int mi = 0; mi < 2; ++mi) {
        int r0i = wm + mi * 16 + lg;
        int r1i = r0i + 8;
        int t0 = (r0i >> 4) * TILE_B_F + (permc(r0i) & 15);
        int t1 = (r1i >> 4) * TILE_B_F + (permc(r1i) & 15);
        #pragma unroll
        for (int ni = 0; ni < 4; ++ni) {
            int cl = wn + ni * 8 + 2 * tg;
            smem[t0 + cl * 16]        = f2tf(c[mi][ni][0]);
            smem[t0 + (cl + 1) * 16]  = f2tf(c[mi][ni][1]);
            smem[t1 + cl * 16]        = f2tf(c[mi][ni][2]);
            smem[t1 + (cl + 1) * 16]  = f2tf(c[mi][ni][3]);
            c[mi][ni][0] = 0.0f; c[mi][ni][1] = 0.0f;
            c[mi][ni][2] = 0.0f; c[mi][ni][3] = 0.0f;
        }
    }
    __syncthreads();

    // ---- phase 2: acc = adj[b] @ P  (K = 128 nodes, 8 k-tiles) ----
    const float* adjb = g_adj + (size_t)b * Nn * Nn;
    auto load_adj = [&](int it, int buf) {
        int k0 = it * BK;
        LOAD_A_TILE(sAdj[buf], adjb, Nn, k0);
        CP_COMMIT();
    };

    load_adj(0, 0);
    load_adj(1, 1);
    load_adj(2, 2);
    for (int it = 0; it < 8; ++it) {
        int buf = it & (NST - 1);
        if (it == 7) { CP_WAIT(0); } else { CP_WAIT(2); }
        __syncthreads();
        if (it + 3 < 8) load_adj(it + 3, (it + 3) & (NST - 1));

        const float* as = smem + REGION0_F + buf * TILE_A_F;
        const float* bs = smem + it * TILE_B_F;
        MMA_TILE_BODY(as, bs);
    }

    // ---- epilogue: residual + relu + bias ----
    #pragma unroll
    for (int mi = 0; mi < 2; ++mi) {
        int r = wm + mi * 16 + lg;
        float id0 = 1.0f / g_denom[b * Nn + r];
        float id1 = 1.0f / g_denom[b * Nn + r + 8];
        size_t row0 = (size_t)(b * Nn + r);
        size_t row1 = row0 + 8;
        #pragma unroll
        for (int ni = 0; ni < 4; ++ni) {
            int cc = blockIdx.x * BN + wn + ni * 8 + 2 * tg;
            float n0 = Xin[row0 * Dn + cc]     + fmaxf(c[mi][ni][0] * id0 + bias[cc], 0.0f);
            float n1 = Xin[row0 * Dn + cc + 1] + fmaxf(c[mi][ni][1] * id0 + bias[cc + 1], 0.0f);
            float n2 = Xin[row1 * Dn + cc]     + fmaxf(c[mi][ni][2] * id1 + bias[cc], 0.0f);
            float n3 = Xin[row1 * Dn + cc + 1] + fmaxf(c[mi][ni][3] * id1 + bias[cc + 1], 0.0f);
            Xout[row0 * Dn + cc]     = n0;
            Xout[row0 * Dn + cc + 1] = n1;
            Xout[row1 * Dn + cc]     = n2;
            Xout[row1 * Dn + cc + 1] = n3;
            if (WXR) {
                XRout[row0 * Dn + permc(cc)]     = f2tf(n0);
                XRout[row0 * Dn + permc(cc + 1)] = f2tf(n1);
                XRout[row1 * Dn + permc(cc)]     = f2tf(n2);
                XRout[row1 * Dn + permc(cc + 1)] = f2tf(n3);
            }
        }
    }
}

// ===========================================================================
// head: gcn_target (node-span sum) + concat + fc + tanh (reads Xfinal)
// ===========================================================================
__global__ void head_kernel(const float* __restrict__ Xfinal,
                            const float* __restrict__ fcW, const float* __restrict__ fcb,
                            const int* __restrict__ gspan, float* __restrict__ out) {
    int b = blockIdx.x;
    int tid = threadIdx.x;
    int gs = gspan[b * 2];
    int ge = gspan[b * 2 + 1];
    float p0 = 0.0f, p1 = 0.0f, p2 = 0.0f;
    for (int d = tid; d < Dn; d += 256) {
        float tm = g_tmax[(size_t)b * Dn + d];
        float gt = 0.0f;
        for (int n = gs; n < ge; ++n)
            gt += Xfinal[((size_t)b * Nn + n) * Dn + d];
        p0 += tm * fcW[d * On + 0] + gt * fcW[(Dn + d) * On + 0];
        p1 += tm * fcW[d * On + 1] + gt * fcW[(Dn + d) * On + 1];
        p2 += tm * fcW[d * On + 2] + gt * fcW[(Dn + d) * On + 2];
    }
    __shared__ float r0[256], r1[256], r2[256];
    r0[tid] = p0; r1[tid] = p1; r2[tid] = p2;
    __syncthreads();
    #pragma unroll
    for (int st = 128; st > 0; st >>= 1) {
        if (tid < st) { r0[tid] += r0[tid + st]; r1[tid] += r1[tid + st]; r2[tid] += r2[tid + st]; }
        __syncthreads();
    }
    if (tid == 0) {
        out[b * On + 0] = tanhf(r0[0] + fcb[0]);
        out[b * On + 1] = tanhf(r1[0] + fcb[1]);
        out[b * On + 2] = tanhf(r2[0] + fcb[2]);
    }
}

// ===========================================================================
extern "C" void kernel_launch(void* const* d_in, const int* in_sizes, int n_in,
                              void* d_out, int out_size) {
    const float* se    = (const float*)d_in[0];
    const float* dg    = (const float*)d_in[1];
    const float* dg1   = (const float*)d_in[2];
    const float* Wproj = (const float*)d_in[3];
    const float* Wg1   = (const float*)d_in[4];
    const float* bg1   = (const float*)d_in[5];
    const float* Wg2   = (const float*)d_in[6];
    const float* bg2   = (const float*)d_in[7];
    const float* Wg3   = (const float*)d_in[8];
    const float* bg3   = (const float*)d_in[9];
    const float* fcW   = (const float*)d_in[10];
    const float* fcb   = (const float*)d_in[11];
    const int*   tspan = (const int*)d_in[12];
    const int*   tran  = (const int*)d_in[13];
    const int*   gspan = (const int*)d_in[14];
    float* out = (float*)d_out;

    float *pt, *px, *px2, *pxr, *pxr2, *pWt;
    cudaGetSymbolAddress((void**)&pt, g_t);
    cudaGetSymbolAddress((void**)&px, g_x);
    cudaGetSymbolAddress((void**)&px2, g_x2);
    cudaGetSymbolAddress((void**)&pxr, g_xr);
    cudaGetSymbolAddress((void**)&pxr2, g_xr2);
    cudaGetSymbolAddress((void**)&pWt, g_Wt);

    cudaFuncSetAttribute(gemm_proj<48>, cudaFuncAttributeMaxDynamicSharedMemorySize, GEMM_SMEM_BYTES);
    cudaFuncSetAttribute(gcn_fused<1>, cudaFuncAttributeMaxDynamicSharedMemorySize, FUSED_SMEM_BYTES);
    cudaFuncSetAttribute(gcn_fused<0>, cudaFuncAttributeMaxDynamicSharedMemorySize, FUSED_SMEM_BYTES);

    dim3 gg(Dn / BN, 64);   // (8, 64) = 512 tiles

    adj_kernel<<<Bn * Nn, 128>>>(dg, dg1);
    span_kernel<<<Bn * Nn, 256>>>(se, tran);
    tmax_kernel<<<Bn, 256>>>(se, tspan);
    wtrans_kernel<<<dim3(24, 24, 4), dim3(32, 8)>>>(Wproj, Wg1, Wg2, Wg3);

    const size_t WSZ = (size_t)Dn * Dn;

    // x = relu(tmps @ W_proj)  -> (g_x, g_xr)
    gemm_proj<48><<<gg, NTHR, GEMM_SMEM_BYTES>>>(pt, pWt + 0 * WSZ, px, pxr);

    // 3 fused GCN layers, ping-pong buffers (inputs never written in-kernel)
    gcn_fused<1><<<gg, NTHR, FUSED_SMEM_BYTES>>>(pxr,  px,  px2, pxr2, pWt + 1 * WSZ, bg1);
    gcn_fused<1><<<gg, NTHR, FUSED_SMEM_BYTES>>>(pxr2, px2, px,  pxr,  pWt + 2 * WSZ, bg2);
    gcn_fused<0><<<gg, NTHR, FUSED_SMEM_BYTES>>>(pxr,  px,  px2, nullptr, pWt + 3 * WSZ, bg3);

    head_kernel<<<Bn, 256>>>(px2, fcW, fcb, gspan, out);
}

// round 15
// speedup vs baseline: 1.4191x; 1.4191x over previous
#include <cuda_runtime.h>
#include <cuda_fp16.h>
#include <cstdint>

// Problem constants
#define Bn 64
#define Sn 512
#define Nn 128
#define Dn 768
#define On 3

// Scratch (device globals -- no allocations allowed)
__device__ float  g_x[(size_t)Bn * Nn * Dn];     // exact node features (ping)
__device__ float  g_x2[(size_t)Bn * Nn * Dn];    // exact node features (pong)
__device__ __half g_xrh[(size_t)Bn * Nn * Dn];   // fp16, K-permuted (ping)
__device__ __half g_xrh2[(size_t)Bn * Nn * Dn];  // fp16, K-permuted (pong)
__device__ __half g_th[(size_t)Bn * Nn * Dn];    // span sums, fp16 permuted
__device__ __half g_adjh[(size_t)Bn * Nn * Nn];  // adjacency fp16 (0/1 exact), permuted
__device__ float  g_denom[(size_t)Bn * Nn];      // row-degree + 1e-7
__device__ float  g_tmax[(size_t)Bn * Dn];       // target max-pool
__device__ __half g_Wth[4 * (size_t)Dn * Dn];    // W^T [N,K] fp16, K-permuted

// ===========================================================================
// helpers
// ===========================================================================
__device__ __forceinline__ uint32_t smem_u32(const void* p) {
    uint32_t a;
    asm("{ .reg .u64 t; cvta.to.shared.u64 t, %1; cvt.u32.u64 %0, t; }" : "=r"(a) : "l"(p));
    return a;
}
// fp16 k16 fragment permutation within each 16-group:
// logical k = 2t+d+8e (t=0..3,d=0..1,e=0..1) -> phys 4t+2e+d
__device__ __forceinline__ int phys16(int j) {
    return (((j & 7) >> 1) << 2) | (((j >> 3) & 1) << 1) | (j & 1);
}
__device__ __forceinline__ int permh(int k) {
    return (k & ~15) | phys16(k & 15);
}
#define CP_ASYNC16(dst, src) \
    asm volatile("cp.async.cg.shared.global [%0], [%1], 16;" :: "r"(dst), "l"(src) : "memory")
#define CP_COMMIT() asm volatile("cp.async.commit_group;" ::: "memory")
#define CP_WAIT(n)  asm volatile("cp.async.wait_group %0;" :: "n"(n) : "memory")

__device__ __forceinline__ void mma_f16(float& c0, float& c1, float& c2, float& c3,
                                        uint32_t a0, uint32_t a1, uint32_t a2, uint32_t a3,
                                        uint32_t b0, uint32_t b1) {
    asm volatile(
        "mma.sync.aligned.m16n8k16.row.col.f32.f16.f16.f32 "
        "{%0,%1,%2,%3}, {%4,%5,%6,%7}, {%8,%9}, {%0,%1,%2,%3};"
        : "+f"(c0), "+f"(c1), "+f"(c2), "+f"(c3)
        : "r"(a0), "r"(a1), "r"(a2), "r"(a3), "r"(b0), "r"(b1));
}

// ===========================================================================
// small prep kernels
// ===========================================================================
__global__ void adj_kernel(const float* __restrict__ dg, const float* __restrict__ dg1) {
    int row = blockIdx.x;
    int tid = threadIdx.x;
    float a = dg[(size_t)row * Nn + tid] + dg1[(size_t)row * Nn + tid];
    a = fminf(a, 1.0f);
    g_adjh[(size_t)row * Nn + permh(tid)] = __float2half_rn(a);
    __shared__ float s[128];
    s[tid] = a;
    __syncthreads();
    #pragma unroll
    for (int st = 64; st > 0; st >>= 1) {
        if (tid < st) s[tid] += s[tid + st];
        __syncthreads();
    }
    if (tid == 0) g_denom[row] = s[0] + 1e-7f;
}

__global__ void span_kernel(const float* __restrict__ se, const int* __restrict__ tran) {
    int row = blockIdx.x;
    int b = row >> 7;
    int s0 = tran[row * 2] + 1;
    int e0 = tran[row * 2 + 1] + 1;
    for (int d = threadIdx.x; d < Dn; d += 256) {
        float acc = 0.0f;
        for (int s = s0; s < e0; ++s)
            acc += se[((size_t)b * Sn + s) * Dn + d];
        g_th[(size_t)row * Dn + permh(d)] = __float2half_rn(acc);
    }
}

__global__ void tmax_kernel(const float* __restrict__ se, const int* __restrict__ tspan) {
    int b = blockIdx.x;
    int l = tspan[b * 2];
    int r = tspan[b * 2 + 1];
    for (int d = threadIdx.x; d < Dn; d += 256) {
        float m = -3.402823466e38f;
        for (int s = l; s < r; ++s)
            m = fmaxf(m, se[((size_t)b * Sn + s) * Dn + d]);
        g_tmax[(size_t)b * Dn + d] = m;
    }
}

// transpose + fp16 + K-permute 4 weight matrices [K=768, N=768] -> g_Wth[w][N][Kperm]
__global__ void wtrans_kernel(const float* __restrict__ W0, const float* __restrict__ W1,
                              const float* __restrict__ W2, const float* __restrict__ W3) {
    __shared__ float t[32][33];
    int w = blockIdx.z;
    const float* W = (w == 0) ? W0 : (w == 1) ? W1 : (w == 2) ? W2 : W3;
    __half* O = g_Wth + (size_t)w * Dn * Dn;
    int nx = blockIdx.x * 32;
    int ky = blockIdx.y * 32;
    int tx = threadIdx.x;
    for (int i = threadIdx.y; i < 32; i += 8)
        t[i][tx] = W[(size_t)(ky + i) * Dn + nx + tx];
    __syncthreads();
    for (int i = threadIdx.y; i < 32; i += 8)
        O[(size_t)(nx + i) * Dn + permh(ky + tx)] = __float2half_rn(t[tx][i]);
}

// ===========================================================================
// fp16 tile geometry: 128(M) x 96(N), BK=32 halves, 256 threads (8 warps 32x48)
// row stride 48 halves (96B): conflict-free LDS.64 fragments + cp.async
// ===========================================================================
#define BKH 32
#define TSH 48
#define BN 96
#define A_TILE_H (128 * TSH)              // 6144 halves
#define B_TILE_H (BN * TSH)               // 4608 halves
#define STAGE_H (A_TILE_H + B_TILE_H)     // 10752 halves
#define NST 3
#define REGION0_H (NST * STAGE_H)         // 32256 halves (64512 B)
#define PT_CHUNK_H (BN * TSH)             // 4608 halves per node-k chunk
#define GEMM_SMEM_BYTES (REGION0_H * 2)                      // 64512
#define FUSED_SMEM_BYTES ((REGION0_H + NST * A_TILE_H) * 2)  // 101376

// per-k32-tile MMA body: 2 fp16 k16-steps; warp tile 32x48
#define MMA_TILE_BODY(ash, bsh)                                                         \
    do {                                                                                \
        _Pragma("unroll")                                                               \
        for (int s = 0; s < 2; ++s) {                                                   \
            uint2 ar0[2], ar1[2], bv[6];                                                \
            _Pragma("unroll")                                                           \
            for (int mi = 0; mi < 2; ++mi) {                                            \
                ar0[mi] = *(const uint2*)&(ash)[(wm + mi * 16 + lg) * TSH + s * 16 + 4 * tg]; \
                ar1[mi] = *(const uint2*)&(ash)[(wm + mi * 16 + lg + 8) * TSH + s * 16 + 4 * tg]; \
            }                                                                           \
            _Pragma("unroll")                                                           \
            for (int ni = 0; ni < 6; ++ni)                                              \
                bv[ni] = *(const uint2*)&(bsh)[(wn + ni * 8 + lg) * TSH + s * 16 + 4 * tg]; \
            _Pragma("unroll")                                                           \
            for (int mi = 0; mi < 2; ++mi)                                              \
                _Pragma("unroll")                                                       \
                for (int ni = 0; ni < 6; ++ni)                                          \
                    mma_f16(c[mi][ni][0], c[mi][ni][1], c[mi][ni][2], c[mi][ni][3],     \
                            ar0[mi].x, ar1[mi].x, ar0[mi].y, ar1[mi].y,                 \
                            bv[ni].x, bv[ni].y);                                        \
        }                                                                               \
    } while (0)

// loaders (256 threads); data = 64B/row at 96B stride; ld in halves
#define LOAD_A_TILE(sbase, ptr, ld, k0)                                                \
    do {                                                                               \
        _Pragma("unroll")                                                              \
        for (int i = 0; i < 2; ++i) {                                                  \
            int id = tid + i * 256;                                                    \
            int row = id >> 2;                                                         \
            int seg = id & 3;                                                          \
            CP_ASYNC16((sbase) + (row * TSH + seg * 8) * 2,                            \
                       (ptr) + (size_t)row * (ld) + (k0) + seg * 8);                   \
        }                                                                              \
    } while (0)

#define LOAD_B_TILE(sbase, ptr, ld, k0)                                                \
    do {                                                                               \
        int row = tid >> 2;                                                            \
        int seg = tid & 3;                                                             \
        CP_ASYNC16((sbase) + (row * TSH + seg * 8) * 2,                                \
                   (ptr) + (size_t)row * (ld) + (k0) + seg * 8);                       \
        if (tid < 128) {                                                               \
            int id2 = tid + 256;                                                       \
            int row2 = id2 >> 2;                                                       \
            int seg2 = id2 & 3;                                                        \
            CP_ASYNC16((sbase) + (row2 * TSH + seg2 * 8) * 2,                          \
                       (ptr) + (size_t)row2 * (ld) + (k0) + seg2 * 8);                 \
        }                                                                              \
    } while (0)

// ===========================================================================
// projection GEMM: Xout = relu(g_th @ Wproj^T); XRout = fp16 permuted copy
// ===========================================================================
template <int KTILES>
__global__ void __launch_bounds__(256, 2)
gemm_proj(const __half* __restrict__ A, const __half* __restrict__ B,
          float* __restrict__ Xout, __half* __restrict__ XRout) {
    extern __shared__ __half smh[];
    int tid = threadIdx.x;
    int lane = tid & 31;
    int warp = tid >> 5;
    int wm = (warp >> 1) * 32;
    int wn = (warp & 1) * 48;
    int lg = lane >> 2;
    int tg = lane & 3;

    const __half* Ab = A + (size_t)blockIdx.y * 128 * Dn;
    const __half* Bb = B + (size_t)blockIdx.x * BN * Dn;

    float c[2][6][4];
    #pragma unroll
    for (int i = 0; i < 2; ++i)
        #pragma unroll
        for (int j = 0; j < 6; ++j)
            #pragma unroll
            for (int k = 0; k < 4; ++k) c[i][j][k] = 0.0f;

    uint32_t sAb[NST], sBb[NST];
    #pragma unroll
    for (int s = 0; s < NST; ++s) {
        sAb[s] = smem_u32(smh + s * STAGE_H);
        sBb[s] = smem_u32(smh + s * STAGE_H + A_TILE_H);
    }

    auto load_stage = [&](int it, int buf) {
        int k0 = it * BKH;
        LOAD_A_TILE(sAb[buf], Ab, Dn, k0);
        LOAD_B_TILE(sBb[buf], Bb, Dn, k0);
        CP_COMMIT();
    };

    load_stage(0, 0);
    load_stage(1, 1);
    for (int it = 0; it < KTILES; ++it) {
        int buf = it % NST;
        if (it == KTILES - 1) { CP_WAIT(0); } else { CP_WAIT(1); }
        __syncthreads();
        if (it + 2 < KTILES) load_stage(it + 2, (it + 2) % NST);

        const __half* ash = smh + buf * STAGE_H;
        const __half* bsh = smh + buf * STAGE_H + A_TILE_H;
        MMA_TILE_BODY(ash, bsh);
    }

    size_t row0 = (size_t)blockIdx.y * 128;
    #pragma unroll
    for (int mi = 0; mi < 2; ++mi) {
        int r = wm + mi * 16 + lg;
        #pragma unroll
        for (int ni = 0; ni < 6; ++ni) {
            int cc = blockIdx.x * BN + wn + ni * 8 + 2 * tg;
            float v0 = fmaxf(c[mi][ni][0], 0.0f);
            float v1 = fmaxf(c[mi][ni][1], 0.0f);
            float v2 = fmaxf(c[mi][ni][2], 0.0f);
            float v3 = fmaxf(c[mi][ni][3], 0.0f);
            Xout[(row0 + r) * Dn + cc]          = v0;
            Xout[(row0 + r) * Dn + cc + 1]      = v1;
            Xout[(row0 + r + 8) * Dn + cc]      = v2;
            Xout[(row0 + r + 8) * Dn + cc + 1]  = v3;
            XRout[(row0 + r) * Dn + permh(cc)]         = __float2half_rn(v0);
            XRout[(row0 + r) * Dn + permh(cc + 1)]     = __float2half_rn(v1);
            XRout[(row0 + r + 8) * Dn + permh(cc)]     = __float2half_rn(v2);
            XRout[(row0 + r + 8) * Dn + permh(cc + 1)] = __float2half_rn(v3);
        }
    }
}

// ===========================================================================
// FUSED GCN layer (ping-pong, race-free): per (dtile=blockIdx.x, b=blockIdx.y)
//   phase 1: P = XRin[b] @ Wg^T   (24 k32-tiles)
//   stage:   P^T (fp16, node-permuted) into region0 as 4 chunks [96][32@TSH]
//   phase 2: acc = adjh[b] @ P    (4 k32-tiles, adj pipeline in region1)
//   epilogue: Xout = Xin + relu(acc/denom + bias); XRout fp16 copy if WXR
// ===========================================================================
template <int WXR>
__global__ void __launch_bounds__(256, 2)
gcn_fused(const __half* __restrict__ XRin, const float* __restrict__ Xin,
          float* __restrict__ Xout, __half* __restrict__ XRout,
          const __half* __restrict__ B, const float* __restrict__ bias) {
    extern __shared__ __half smh[];
    int tid = threadIdx.x;
    int lane = tid & 31;
    int warp = tid >> 5;
    int wm = (warp >> 1) * 32;
    int wn = (warp & 1) * 48;
    int lg = lane >> 2;
    int tg = lane & 3;

    int b = blockIdx.y;
    const __half* Ab = XRin + (size_t)b * 128 * Dn;
    const __half* Bb = B + (size_t)blockIdx.x * BN * Dn;

    float c[2][6][4];
    #pragma unroll
    for (int i = 0; i < 2; ++i)
        #pragma unroll
        for (int j = 0; j < 6; ++j)
            #pragma unroll
            for (int k = 0; k < 4; ++k) c[i][j][k] = 0.0f;

    uint32_t sAb[NST], sBb[NST], sAdj[NST];
    #pragma unroll
    for (int s = 0; s < NST; ++s) {
        sAb[s]  = smem_u32(smh + s * STAGE_H);
        sBb[s]  = smem_u32(smh + s * STAGE_H + A_TILE_H);
        sAdj[s] = smem_u32(smh + REGION0_H + s * A_TILE_H);
    }

    // ---- phase 1: P = XRin[b] @ W^T ----
    auto load_stage = [&](int it, int buf) {
        int k0 = it * BKH;
        LOAD_A_TILE(sAb[buf], Ab, Dn, k0);
        LOAD_B_TILE(sBb[buf], Bb, Dn, k0);
        CP_COMMIT();
    };

    load_stage(0, 0);
    load_stage(1, 1);
    const int KT1 = Dn / BKH;   // 24
    for (int it = 0; it < KT1; ++it) {
        int buf = it % NST;
        if (it == KT1 - 1) { CP_WAIT(0); } else { CP_WAIT(1); }
        __syncthreads();
        if (it + 2 < KT1) load_stage(it + 2, (it + 2) % NST);

        const __half* ash = smh + buf * STAGE_H;
        const __half* bsh = smh + buf * STAGE_H + A_TILE_H;
        MMA_TILE_BODY(ash, bsh);
    }
    __syncthreads();

    // ---- stage P^T into region0: 4 node-k chunks of [96 d-rows][32 halves @ TSH] ----
    // node m -> chunk m>>5, within-chunk pos (m&16)|phys16(m&15)
    #pragma unroll
    for (int mi = 0; mi < 2; ++mi) {
        int m0 = wm + mi * 16 + lg;
        int m1 = m0 + 8;
        int p0 = (m0 >> 5) * PT_CHUNK_H + ((m0 & 16) | phys16(m0 & 15));
        int p1 = (m1 >> 5) * PT_CHUNK_H + ((m1 & 16) | phys16(m1 & 15));
        #pragma unroll
        for (int ni = 0; ni < 6; ++ni) {
            int dl = wn + ni * 8 + 2 * tg;
            smh[p0 + dl * TSH]       = __float2half_rn(c[mi][ni][0]);
            smh[p0 + (dl + 1) * TSH] = __float2half_rn(c[mi][ni][1]);
            smh[p1 + dl * TSH]       = __float2half_rn(c[mi][ni][2]);
            smh[p1 + (dl + 1) * TSH] = __float2half_rn(c[mi][ni][3]);
            c[mi][ni][0] = 0.0f; c[mi][ni][1] = 0.0f;
            c[mi][ni][2] = 0.0f; c[mi][ni][3] = 0.0f;
        }
    }
    __syncthreads();

    // ---- phase 2: acc = adjh[b] @ P  (K = 128 nodes, 4 k32-tiles) ----
    const __half* adjb = g_adjh + (size_t)b * Nn * Nn;
    auto load_adj = [&](int it, int buf) {
        int k0 = it * BKH;
        LOAD_A_TILE(sAdj[buf], adjb, Nn, k0);
        CP_COMMIT();
    };

    load_adj(0, 0);
    load_adj(1, 1);
    for (int it = 0; it < 4; ++it) {
        int buf = it % NST;
        if (it == 3) { CP_WAIT(0); } else { CP_WAIT(1); }
        __syncthreads();
        if (it + 2 < 4) load_adj(it + 2, (it + 2) % NST);

        const __half* ash = smh + REGION0_H + buf * A_TILE_H;
        const __half* bsh = smh + it * PT_CHUNK_H;
        MMA_TILE_BODY(ash, bsh);
    }

    // ---- epilogue: residual + relu + bias ----
    #pragma unroll
    for (int mi = 0; mi < 2; ++mi) {
        int r = wm + mi * 16 + lg;
        float id0 = 1.0f / g_denom[b * Nn + r];
        float id1 = 1.0f / g_denom[b * Nn + r + 8];
        size_t row0 = (size_t)(b * Nn + r);
        size_t row1 = row0 + 8;
        #pragma unroll
        for (int ni = 0; ni < 6; ++ni) {
            int cc = blockIdx.x * BN + wn + ni * 8 + 2 * tg;
            float n0 = Xin[row0 * Dn + cc]     + fmaxf(c[mi][ni][0] * id0 + bias[cc], 0.0f);
            float n1 = Xin[row0 * Dn + cc + 1] + fmaxf(c[mi][ni][1] * id0 + bias[cc + 1], 0.0f);
            float n2 = Xin[row1 * Dn + cc]     + fmaxf(c[mi][ni][2] * id1 + bias[cc], 0.0f);
            float n3 = Xin[row1 * Dn + cc + 1] + fmaxf(c[mi][ni][3] * id1 + bias[cc + 1], 0.0f);
            Xout[row0 * Dn + cc]     = n0;
            Xout[row0 * Dn + cc + 1] = n1;
            Xout[row1 * Dn + cc]     = n2;
            Xout[row1 * Dn + cc + 1] = n3;
            if (WXR) {
                XRout[row0 * Dn + permh(cc)]     = __float2half_rn(n0);
                XRout[row0 * Dn + permh(cc + 1)] = __float2half_rn(n1);
                XRout[row1 * Dn + permh(cc)]     = __float2half_rn(n2);
                XRout[row1 * Dn + permh(cc + 1)] = __float2half_rn(n3);
            }
        }
    }
}

// ===========================================================================
// head: gcn_target (node-span sum) + concat + fc + tanh (reads Xfinal)
// ===========================================================================
__global__ void head_kernel(const float* __restrict__ Xfinal,
                            const float* __restrict__ fcW, const float* __restrict__ fcb,
                            const int* __restrict__ gspan, float* __restrict__ out) {
    int b = blockIdx.x;
    int tid = threadIdx.x;
    int gs = gspan[b * 2];
    int ge = gspan[b * 2 + 1];
    float p0 = 0.0f, p1 = 0.0f, p2 = 0.0f;
    for (int d = tid; d < Dn; d += 256) {
        float tm = g_tmax[(size_t)b * Dn + d];
        float gt = 0.0f;
        for (int n = gs; n < ge; ++n)
            gt += Xfinal[((size_t)b * Nn + n) * Dn + d];
        p0 += tm * fcW[d * On + 0] + gt * fcW[(Dn + d) * On + 0];
        p1 += tm * fcW[d * On + 1] + gt * fcW[(Dn + d) * On + 1];
        p2 += tm * fcW[d * On + 2] + gt * fcW[(Dn + d) * On + 2];
    }
    __shared__ float r0[256], r1[256], r2[256];
    r0[tid] = p0; r1[tid] = p1; r2[tid] = p2;
    __syncthreads();
    #pragma unroll
    for (int st = 128; st > 0; st >>= 1) {
        if (tid < st) { r0[tid] += r0[tid + st]; r1[tid] += r1[tid + st]; r2[tid] += r2[tid + st]; }
        __syncthreads();
    }
    if (tid == 0) {
        out[b * On + 0] = tanhf(r0[0] + fcb[0]);
        out[b * On + 1] = tanhf(r1[0] + fcb[1]);
        out[b * On + 2] = tanhf(r2[0] + fcb[2]);
    }
}

// ===========================================================================
extern "C" void kernel_launch(void* const* d_in, const int* in_sizes, int n_in,
                              void* d_out, int out_size) {
    const float* se    = (const float*)d_in[0];
    const float* dg    = (const float*)d_in[1];
    const float* dg1   = (const float*)d_in[2];
    const float* Wproj = (const float*)d_in[3];
    const float* Wg1   = (const float*)d_in[4];
    const float* bg1   = (const float*)d_in[5];
    const float* Wg2   = (const float*)d_in[6];
    const float* bg2   = (const float*)d_in[7];
    const float* Wg3   = (const float*)d_in[8];
    const float* bg3   = (const float*)d_in[9];
    const float* fcW   = (const float*)d_in[10];
    const float* fcb   = (const float*)d_in[11];
    const int*   tspan = (const int*)d_in[12];
    const int*   tran  = (const int*)d_in[13];
    const int*   gspan = (const int*)d_in[14];
    float* out = (float*)d_out;

    float *px, *px2;
    __half *pth, *pxrh, *pxrh2, *pWth;
    cudaGetSymbolAddress((void**)&px, g_x);
    cudaGetSymbolAddress((void**)&px2, g_x2);
    cudaGetSymbolAddress((void**)&pth, g_th);
    cudaGetSymbolAddress((void**)&pxrh, g_xrh);
    cudaGetSymbolAddress((void**)&pxrh2, g_xrh2);
    cudaGetSymbolAddress((void**)&pWth, g_Wth);

    cudaFuncSetAttribute(gemm_proj<24>, cudaFuncAttributeMaxDynamicSharedMemorySize, GEMM_SMEM_BYTES);
    cudaFuncSetAttribute(gcn_fused<1>, cudaFuncAttributeMaxDynamicSharedMemorySize, FUSED_SMEM_BYTES);
    cudaFuncSetAttribute(gcn_fused<0>, cudaFuncAttributeMaxDynamicSharedMemorySize, FUSED_SMEM_BYTES);

    dim3 gg(Dn / BN, 64);   // (8, 64) = 512 tiles

    adj_kernel<<<Bn * Nn, 128>>>(dg, dg1);
    span_kernel<<<Bn * Nn, 256>>>(se, tran);
    tmax_kernel<<<Bn, 256>>>(se, tspan);
    wtrans_kernel<<<dim3(24, 24, 4), dim3(32, 8)>>>(Wproj, Wg1, Wg2, Wg3);

    const size_t WSZ = (size_t)Dn * Dn;

    // x = relu(tmps @ W_proj)  -> (g_x, g_xrh)
    gemm_proj<24><<<gg, 256, GEMM_SMEM_BYTES>>>(pth, pWth + 0 * WSZ, px, pxrh);

    // 3 fused GCN layers, ping-pong buffers (inputs never written in-kernel)
    gcn_fused<1><<<gg, 256, FUSED_SMEM_BYTES>>>(pxrh,  px,  px2, pxrh2, pWth + 1 * WSZ, bg1);
    gcn_fused<1><<<gg, 256, FUSED_SMEM_BYTES>>>(pxrh2, px2, px,  pxrh,  pWth + 2 * WSZ, bg2);
    gcn_fused<0><<<gg, 256, FUSED_SMEM_BYTES>>>(pxrh,  px,  px2, nullptr, pWth + 3 * WSZ, bg3);

    head_kernel<<<Bn, 256>>>(px2, fcW, fcb, gspan, out);
}

// round 16
// speedup vs baseline: 1.4512x; 1.0226x over previous
#include <cuda_runtime.h>
#include <cuda_fp16.h>
#include <cstdint>

// Problem constants
#define Bn 64
#define Sn 512
#define Nn 128
#define Dn 768
#define On 3

// Scratch (device globals -- no allocations allowed)
__device__ float  g_x[(size_t)Bn * Nn * Dn];     // exact node features (ping)
__device__ float  g_x2[(size_t)Bn * Nn * Dn];    // exact node features (pong)
__device__ __half g_xrh[(size_t)Bn * Nn * Dn];   // fp16, K-permuted (ping)
__device__ __half g_xrh2[(size_t)Bn * Nn * Dn];  // fp16, K-permuted (pong)
__device__ __half g_th[(size_t)Bn * Nn * Dn];    // span sums, fp16 permuted
__device__ __half g_adjh[(size_t)Bn * Nn * Nn];  // adjacency fp16 (0/1 exact), permuted
__device__ float  g_denom[(size_t)Bn * Nn];      // row-degree + 1e-7
__device__ float  g_tmax[(size_t)Bn * Dn];       // target max-pool
__device__ __half g_Wth[4 * (size_t)Dn * Dn];    // W^T [N,K] fp16, K-permuted

// ===========================================================================
// helpers
// ===========================================================================
__device__ __forceinline__ uint32_t smem_u32(const void* p) {
    uint32_t a;
    asm("{ .reg .u64 t; cvta.to.shared.u64 t, %1; cvt.u32.u64 %0, t; }" : "=r"(a) : "l"(p));
    return a;
}
// fp16 k16 fragment permutation within each 16-group:
// logical k = 2t+d+8e (t=0..3,d=0..1,e=0..1) -> phys 4t+2e+d
__device__ __forceinline__ int phys16(int j) {
    return (((j & 7) >> 1) << 2) | (((j >> 3) & 1) << 1) | (j & 1);
}
__device__ __forceinline__ int permh(int k) {
    return (k & ~15) | phys16(k & 15);
}
#define CP_ASYNC16(dst, src) \
    asm volatile("cp.async.cg.shared.global [%0], [%1], 16;" :: "r"(dst), "l"(src) : "memory")
#define CP_COMMIT() asm volatile("cp.async.commit_group;" ::: "memory")
#define CP_WAIT(n)  asm volatile("cp.async.wait_group %0;" :: "n"(n) : "memory")

__device__ __forceinline__ void mma_f16(float& c0, float& c1, float& c2, float& c3,
                                        uint32_t a0, uint32_t a1, uint32_t a2, uint32_t a3,
                                        uint32_t b0, uint32_t b1) {
    asm volatile(
        "mma.sync.aligned.m16n8k16.row.col.f32.f16.f16.f32 "
        "{%0,%1,%2,%3}, {%4,%5,%6,%7}, {%8,%9}, {%0,%1,%2,%3};"
        : "+f"(c0), "+f"(c1), "+f"(c2), "+f"(c3)
        : "r"(a0), "r"(a1), "r"(a2), "r"(a3), "r"(b0), "r"(b1));
}

// ===========================================================================
// MERGED prep kernel: adj + span + tmax + wtrans in one launch (overlapped)
// grid layout: [0,4096) adj (2 rows/block), [4096,12288) span,
//              [12288,12352) tmax, [12352,14656) wtrans
// 256 threads everywhere
// ===========================================================================
#define PREP_ADJ_BLKS   4096
#define PREP_SPAN_BLKS  8192
#define PREP_TMAX_BLKS  64
#define PREP_WT_BLKS    2304
#define PREP_GRID (PREP_ADJ_BLKS + PREP_SPAN_BLKS + PREP_TMAX_BLKS + PREP_WT_BLKS)

__global__ void prep_kernel(const float* __restrict__ se,
                            const float* __restrict__ dg, const float* __restrict__ dg1,
                            const float* __restrict__ W0, const float* __restrict__ W1,
                            const float* __restrict__ W2, const float* __restrict__ W3,
                            const int* __restrict__ tspan, const int* __restrict__ tran) {
    int blk = blockIdx.x;
    int tid = threadIdx.x;

    if (blk < PREP_ADJ_BLKS) {
        // ---- adjacency: 2 rows per block (128 threads each) ----
        int row = blk * 2 + (tid >> 7);
        int col = tid & 127;
        float a = dg[(size_t)row * Nn + col] + dg1[(size_t)row * Nn + col];
        a = fminf(a, 1.0f);
        g_adjh[(size_t)row * Nn + permh(col)] = __float2half_rn(a);
        __shared__ float s[256];
        s[tid] = a;
        __syncthreads();
        #pragma unroll
        for (int st = 64; st > 0; st >>= 1) {
            if ((tid & 127) < st) s[tid] += s[tid + st];
            __syncthreads();
        }
        if ((tid & 127) == 0) g_denom[row] = s[tid] + 1e-7f;
    } else if (blk < PREP_ADJ_BLKS + PREP_SPAN_BLKS) {
        // ---- span sums ----
        int row = blk - PREP_ADJ_BLKS;
        int b = row >> 7;
        int s0 = tran[row * 2] + 1;
        int e0 = tran[row * 2 + 1] + 1;
        for (int d = tid; d < Dn; d += 256) {
            float acc = 0.0f;
            for (int s = s0; s < e0; ++s)
                acc += se[((size_t)b * Sn + s) * Dn + d];
            g_th[(size_t)row * Dn + permh(d)] = __float2half_rn(acc);
        }
    } else if (blk < PREP_ADJ_BLKS + PREP_SPAN_BLKS + PREP_TMAX_BLKS) {
        // ---- target max-pool ----
        int b = blk - (PREP_ADJ_BLKS + PREP_SPAN_BLKS);
        int l = tspan[b * 2];
        int r = tspan[b * 2 + 1];
        for (int d = tid; d < Dn; d += 256) {
            float m = -3.402823466e38f;
            for (int s = l; s < r; ++s)
                m = fmaxf(m, se[((size_t)b * Sn + s) * Dn + d]);
            g_tmax[(size_t)b * Dn + d] = m;
        }
    } else {
        // ---- weight transpose + fp16 + K-permute ----
        int idx = blk - (PREP_ADJ_BLKS + PREP_SPAN_BLKS + PREP_TMAX_BLKS);
        int w = idx / 576;            // 24*24 = 576 per weight
        int rem = idx % 576;
        int by = rem / 24;
        int bx = rem % 24;
        int tx = tid & 31;
        int ty = tid >> 5;            // 0..7
        __shared__ float t[32][33];
        const float* W = (w == 0) ? W0 : (w == 1) ? W1 : (w == 2) ? W2 : W3;
        __half* O = g_Wth + (size_t)w * Dn * Dn;
        int nx = bx * 32;
        int ky = by * 32;
        for (int i = ty; i < 32; i += 8)
            t[i][tx] = W[(size_t)(ky + i) * Dn + nx + tx];
        __syncthreads();
        for (int i = ty; i < 32; i += 8)
            O[(size_t)(nx + i) * Dn + permh(ky + tx)] = __float2half_rn(t[tx][i]);
    }
}

// ===========================================================================
// fp16 tile geometry: 128(M) x 96(N), BK=32 halves, 256 threads (8 warps 32x48)
// row stride 48 halves (96B): conflict-free LDS.64 fragments + cp.async
// ===========================================================================
#define BKH 32
#define TSH 48
#define BN 96
#define A_TILE_H (128 * TSH)              // 6144 halves
#define B_TILE_H (BN * TSH)               // 4608 halves
#define STAGE_H (A_TILE_H + B_TILE_H)     // 10752 halves
#define NST 3
#define REGION0_H (NST * STAGE_H)         // 32256 halves (64512 B)
#define PT_CHUNK_H (BN * TSH)             // 4608 halves per node-k chunk
#define GEMM_SMEM_BYTES (REGION0_H * 2)                      // 64512
#define FUSED_SMEM_BYTES ((REGION0_H + NST * A_TILE_H) * 2)  // 101376

// per-k32-tile MMA body: 2 fp16 k16-steps; warp tile 32x48
#define MMA_TILE_BODY(ash, bsh)                                                         \
    do {                                                                                \
        _Pragma("unroll")                                                               \
        for (int s = 0; s < 2; ++s) {                                                   \
            uint2 ar0[2], ar1[2], bv[6];                                                \
            _Pragma("unroll")                                                           \
            for (int mi = 0; mi < 2; ++mi) {                                            \
                ar0[mi] = *(const uint2*)&(ash)[(wm + mi * 16 + lg) * TSH + s * 16 + 4 * tg]; \
                ar1[mi] = *(const uint2*)&(ash)[(wm + mi * 16 + lg + 8) * TSH + s * 16 + 4 * tg]; \
            }                                                                           \
            _Pragma("unroll")                                                           \
            for (int ni = 0; ni < 6; ++ni)                                              \
                bv[ni] = *(const uint2*)&(bsh)[(wn + ni * 8 + lg) * TSH + s * 16 + 4 * tg]; \
            _Pragma("unroll")                                                           \
            for (int mi = 0; mi < 2; ++mi)                                              \
                _Pragma("unroll")                                                       \
                for (int ni = 0; ni < 6; ++ni)                                          \
                    mma_f16(c[mi][ni][0], c[mi][ni][1], c[mi][ni][2], c[mi][ni][3],     \
                            ar0[mi].x, ar1[mi].x, ar0[mi].y, ar1[mi].y,                 \
                            bv[ni].x, bv[ni].y);                                        \
        }                                                                               \
    } while (0)

// loaders (256 threads); data = 64B/row at 96B stride; ld in halves
#define LOAD_A_TILE(sbase, ptr, ld, k0)                                                \
    do {                                                                               \
        _Pragma("unroll")                                                              \
        for (int i = 0; i < 2; ++i) {                                                  \
            int id = tid + i * 256;                                                    \
            int row = id >> 2;                                                         \
            int seg = id & 3;                                                          \
            CP_ASYNC16((sbase) + (row * TSH + seg * 8) * 2,                            \
                       (ptr) + (size_t)row * (ld) + (k0) + seg * 8);                   \
        }                                                                              \
    } while (0)

#define LOAD_B_TILE(sbase, ptr, ld, k0)                                                \
    do {                                                                               \
        int row = tid >> 2;                                                            \
        int seg = tid & 3;                                                             \
        CP_ASYNC16((sbase) + (row * TSH + seg * 8) * 2,                                \
                   (ptr) + (size_t)row * (ld) + (k0) + seg * 8);                       \
        if (tid < 128) {                                                               \
            int id2 = tid + 256;                                                       \
            int row2 = id2 >> 2;                                                       \
            int seg2 = id2 & 3;                                                        \
            CP_ASYNC16((sbase) + (row2 * TSH + seg2 * 8) * 2,                          \
                       (ptr) + (size_t)row2 * (ld) + (k0) + seg2 * 8);                 \
        }                                                                              \
    } while (0)

// ===========================================================================
// projection GEMM: Xout = relu(g_th @ Wproj^T); XRout = fp16 permuted copy
// ===========================================================================
template <int KTILES>
__global__ void __launch_bounds__(256, 2)
gemm_proj(const __half* __restrict__ A, const __half* __restrict__ B,
          float* __restrict__ Xout, __half* __restrict__ XRout) {
    extern __shared__ __half smh[];
    int tid = threadIdx.x;
    int lane = tid & 31;
    int warp = tid >> 5;
    int wm = (warp >> 1) * 32;
    int wn = (warp & 1) * 48;
    int lg = lane >> 2;
    int tg = lane & 3;

    const __half* Ab = A + (size_t)blockIdx.y * 128 * Dn;
    const __half* Bb = B + (size_t)blockIdx.x * BN * Dn;

    float c[2][6][4];
    #pragma unroll
    for (int i = 0; i < 2; ++i)
        #pragma unroll
        for (int j = 0; j < 6; ++j)
            #pragma unroll
            for (int k = 0; k < 4; ++k) c[i][j][k] = 0.0f;

    uint32_t sAb[NST], sBb[NST];
    #pragma unroll
    for (int s = 0; s < NST; ++s) {
        sAb[s] = smem_u32(smh + s * STAGE_H);
        sBb[s] = smem_u32(smh + s * STAGE_H + A_TILE_H);
    }

    auto load_stage = [&](int it, int buf) {
        int k0 = it * BKH;
        LOAD_A_TILE(sAb[buf], Ab, Dn, k0);
        LOAD_B_TILE(sBb[buf], Bb, Dn, k0);
        CP_COMMIT();
    };

    load_stage(0, 0);
    load_stage(1, 1);
    for (int it = 0; it < KTILES; ++it) {
        int buf = it % NST;
        if (it == KTILES - 1) { CP_WAIT(0); } else { CP_WAIT(1); }
        __syncthreads();
        if (it + 2 < KTILES) load_stage(it + 2, (it + 2) % NST);

        const __half* ash = smh + buf * STAGE_H;
        const __half* bsh = smh + buf * STAGE_H + A_TILE_H;
        MMA_TILE_BODY(ash, bsh);
    }

    size_t row0 = (size_t)blockIdx.y * 128;
    #pragma unroll
    for (int mi = 0; mi < 2; ++mi) {
        int r = wm + mi * 16 + lg;
        #pragma unroll
        for (int ni = 0; ni < 6; ++ni) {
            int cc = blockIdx.x * BN + wn + ni * 8 + 2 * tg;
            float v0 = fmaxf(c[mi][ni][0], 0.0f);
            float v1 = fmaxf(c[mi][ni][1], 0.0f);
            float v2 = fmaxf(c[mi][ni][2], 0.0f);
            float v3 = fmaxf(c[mi][ni][3], 0.0f);
            Xout[(row0 + r) * Dn + cc]          = v0;
            Xout[(row0 + r) * Dn + cc + 1]      = v1;
            Xout[(row0 + r + 8) * Dn + cc]      = v2;
            Xout[(row0 + r + 8) * Dn + cc + 1]  = v3;
            XRout[(row0 + r) * Dn + permh(cc)]         = __float2half_rn(v0);
            XRout[(row0 + r) * Dn + permh(cc + 1)]     = __float2half_rn(v1);
            XRout[(row0 + r + 8) * Dn + permh(cc)]     = __float2half_rn(v2);
            XRout[(row0 + r + 8) * Dn + permh(cc + 1)] = __float2half_rn(v3);
        }
    }
}

// ===========================================================================
// FUSED GCN layer (ping-pong, race-free): per (dtile=blockIdx.x, b=blockIdx.y)
// ===========================================================================
template <int WXR>
__global__ void __launch_bounds__(256, 2)
gcn_fused(const __half* __restrict__ XRin, const float* __restrict__ Xin,
          float* __restrict__ Xout, __half* __restrict__ XRout,
          const __half* __restrict__ B, const float* __restrict__ bias) {
    extern __shared__ __half smh[];
    int tid = threadIdx.x;
    int lane = tid & 31;
    int warp = tid >> 5;
    int wm = (warp >> 1) * 32;
    int wn = (warp & 1) * 48;
    int lg = lane >> 2;
    int tg = lane & 3;

    int b = blockIdx.y;
    const __half* Ab = XRin + (size_t)b * 128 * Dn;
    const __half* Bb = B + (size_t)blockIdx.x * BN * Dn;

    float c[2][6][4];
    #pragma unroll
    for (int i = 0; i < 2; ++i)
        #pragma unroll
        for (int j = 0; j < 6; ++j)
            #pragma unroll
            for (int k = 0; k < 4; ++k) c[i][j][k] = 0.0f;

    uint32_t sAb[NST], sBb[NST], sAdj[NST];
    #pragma unroll
    for (int s = 0; s < NST; ++s) {
        sAb[s]  = smem_u32(smh + s * STAGE_H);
        sBb[s]  = smem_u32(smh + s * STAGE_H + A_TILE_H);
        sAdj[s] = smem_u32(smh + REGION0_H + s * A_TILE_H);
    }

    // ---- phase 1: P = XRin[b] @ W^T ----
    auto load_stage = [&](int it, int buf) {
        int k0 = it * BKH;
        LOAD_A_TILE(sAb[buf], Ab, Dn, k0);
        LOAD_B_TILE(sBb[buf], Bb, Dn, k0);
        CP_COMMIT();
    };

    load_stage(0, 0);
    load_stage(1, 1);
    const int KT1 = Dn / BKH;   // 24
    for (int it = 0; it < KT1; ++it) {
        int buf = it % NST;
        if (it == KT1 - 1) { CP_WAIT(0); } else { CP_WAIT(1); }
        __syncthreads();
        if (it + 2 < KT1) load_stage(it + 2, (it + 2) % NST);

        const __half* ash = smh + buf * STAGE_H;
        const __half* bsh = smh + buf * STAGE_H + A_TILE_H;
        MMA_TILE_BODY(ash, bsh);
    }
    __syncthreads();

    // ---- stage P^T into region0: 4 node-k chunks of [96 d-rows][32 halves @ TSH] ----
    // node m -> chunk m>>5, within-chunk pos (m&16)|phys16(m&15)
    #pragma unroll
    for (int mi = 0; mi < 2; ++mi) {
        int m0 = wm + mi * 16 + lg;
        int m1 = m0 + 8;
        int p0 = (m0 >> 5) * PT_CHUNK_H + ((m0 & 16) | phys16(m0 & 15));
        int p1 = (m1 >> 5) * PT_CHUNK_H + ((m1 & 16) | phys16(m1 & 15));
        #pragma unroll
        for (int ni = 0; ni < 6; ++ni) {
            int dl = wn + ni * 8 + 2 * tg;
            smh[p0 + dl * TSH]       = __float2half_rn(c[mi][ni][0]);
            smh[p0 + (dl + 1) * TSH] = __float2half_rn(c[mi][ni][1]);
            smh[p1 + dl * TSH]       = __float2half_rn(c[mi][ni][2]);
            smh[p1 + (dl + 1) * TSH] = __float2half_rn(c[mi][ni][3]);
            c[mi][ni][0] = 0.0f; c[mi][ni][1] = 0.0f;
            c[mi][ni][2] = 0.0f; c[mi][ni][3] = 0.0f;
        }
    }
    __syncthreads();

    // ---- phase 2: acc = adjh[b] @ P  (K = 128 nodes, 4 k32-tiles) ----
    const __half* adjb = g_adjh + (size_t)b * Nn * Nn;
    auto load_adj = [&](int it, int buf) {
        int k0 = it * BKH;
        LOAD_A_TILE(sAdj[buf], adjb, Nn, k0);
        CP_COMMIT();
    };

    load_adj(0, 0);
    load_adj(1, 1);
    for (int it = 0; it < 4; ++it) {
        int buf = it % NST;
        if (it == 3) { CP_WAIT(0); } else { CP_WAIT(1); }
        __syncthreads();
        if (it + 2 < 4) load_adj(it + 2, (it + 2) % NST);

        const __half* ash = smh + REGION0_H + buf * A_TILE_H;
        const __half* bsh = smh + it * PT_CHUNK_H;
        MMA_TILE_BODY(ash, bsh);
    }

    // ---- epilogue: residual + relu + bias ----
    #pragma unroll
    for (int mi = 0; mi < 2; ++mi) {
        int r = wm + mi * 16 + lg;
        float id0 = 1.0f / g_denom[b * Nn + r];
        float id1 = 1.0f / g_denom[b * Nn + r + 8];
        size_t row0 = (size_t)(b * Nn + r);
        size_t row1 = row0 + 8;
        #pragma unroll
        for (int ni = 0; ni < 6; ++ni) {
            int cc = blockIdx.x * BN + wn + ni * 8 + 2 * tg;
            float n0 = Xin[row0 * Dn + cc]     + fmaxf(c[mi][ni][0] * id0 + bias[cc], 0.0f);
            float n1 = Xin[row0 * Dn + cc + 1] + fmaxf(c[mi][ni][1] * id0 + bias[cc + 1], 0.0f);
            float n2 = Xin[row1 * Dn + cc]     + fmaxf(c[mi][ni][2] * id1 + bias[cc], 0.0f);
            float n3 = Xin[row1 * Dn + cc + 1] + fmaxf(c[mi][ni][3] * id1 + bias[cc + 1], 0.0f);
            Xout[row0 * Dn + cc]     = n0;
            Xout[row0 * Dn + cc + 1] = n1;
            Xout[row1 * Dn + cc]     = n2;
            Xout[row1 * Dn + cc + 1] = n3;
            if (WXR) {
                XRout[row0 * Dn + permh(cc)]     = __float2half_rn(n0);
                XRout[row0 * Dn + permh(cc + 1)] = __float2half_rn(n1);
                XRout[row1 * Dn + permh(cc)]     = __float2half_rn(n2);
                XRout[row1 * Dn + permh(cc + 1)] = __float2half_rn(n3);
            }
        }
    }
}

// ===========================================================================
// head: gcn_target (node-span sum) + concat + fc + tanh (reads Xfinal)
// ===========================================================================
__global__ void head_kernel(const float* __restrict__ Xfinal,
                            const float* __restrict__ fcW, const float* __restrict__ fcb,
                            const int* __restrict__ gspan, float* __restrict__ out) {
    int b = blockIdx.x;
    int tid = threadIdx.x;
    int gs = gspan[b * 2];
    int ge = gspan[b * 2 + 1];
    float p0 = 0.0f, p1 = 0.0f, p2 = 0.0f;
    for (int d = tid; d < Dn; d += 256) {
        float tm = g_tmax[(size_t)b * Dn + d];
        float gt = 0.0f;
        for (int n = gs; n < ge; ++n)
            gt += Xfinal[((size_t)b * Nn + n) * Dn + d];
        p0 += tm * fcW[d * On + 0] + gt * fcW[(Dn + d) * On + 0];
        p1 += tm * fcW[d * On + 1] + gt * fcW[(Dn + d) * On + 1];
        p2 += tm * fcW[d * On + 2] + gt * fcW[(Dn + d) * On + 2];
    }
    __shared__ float r0[256], r1[256], r2[256];
    r0[tid] = p0; r1[tid] = p1; r2[tid] = p2;
    __syncthreads();
    #pragma unroll
    for (int st = 128; st > 0; st >>= 1) {
        if (tid < st) { r0[tid] += r0[tid + st]; r1[tid] += r1[tid + st]; r2[tid] += r2[tid + st]; }
        __syncthreads();
    }
    if (tid == 0) {
        out[b * On + 0] = tanhf(r0[0] + fcb[0]);
        out[b * On + 1] = tanhf(r1[0] + fcb[1]);
        out[b * On + 2] = tanhf(r2[0] + fcb[2]);
    }
}

// ===========================================================================
extern "C" void kernel_launch(void* const* d_in, const int* in_sizes, int n_in,
                              void* d_out, int out_size) {
    const float* se    = (const float*)d_in[0];
    const float* dg    = (const float*)d_in[1];
    const float* dg1   = (const float*)d_in[2];
    const float* Wproj = (const float*)d_in[3];
    const float* Wg1   = (const float*)d_in[4];
    const float* bg1   = (const float*)d_in[5];
    const float* Wg2   = (const float*)d_in[6];
    const float* bg2   = (const float*)d_in[7];
    const float* Wg3   = (const float*)d_in[8];
    const float* bg3   = (const float*)d_in[9];
    const float* fcW   = (const float*)d_in[10];
    const float* fcb   = (const float*)d_in[11];
    const int*   tspan = (const int*)d_in[12];
    const int*   tran  = (const int*)d_in[13];
    const int*   gspan = (const int*)d_in[14];
    float* out = (float*)d_out;

    float *px, *px2;
    __half *pth, *pxrh, *pxrh2, *pWth;
    cudaGetSymbolAddress((void**)&px, g_x);
    cudaGetSymbolAddress((void**)&px2, g_x2);
    cudaGetSymbolAddress((void**)&pth, g_th);
    cudaGetSymbolAddress((void**)&pxrh, g_xrh);
    cudaGetSymbolAddress((void**)&pxrh2, g_xrh2);
    cudaGetSymbolAddress((void**)&pWth, g_Wth);

    cudaFuncSetAttribute(gemm_proj<24>, cudaFuncAttributeMaxDynamicSharedMemorySize, GEMM_SMEM_BYTES);
    cudaFuncSetAttribute(gcn_fused<1>, cudaFuncAttributeMaxDynamicSharedMemorySize, FUSED_SMEM_BYTES);
    cudaFuncSetAttribute(gcn_fused<0>, cudaFuncAttributeMaxDynamicSharedMemorySize, FUSED_SMEM_BYTES);

    dim3 gg(Dn / BN, 64);   // (8, 64) = 512 tiles

    // merged prep: adj + span + tmax + wtrans overlapped in one launch
    prep_kernel<<<PREP_GRID, 256>>>(se, dg, dg1, Wproj, Wg1, Wg2, Wg3, tspan, tran);

    const size_t WSZ = (size_t)Dn * Dn;

    // x = relu(tmps @ W_proj)  -> (g_x, g_xrh)
    gemm_proj<24><<<gg, 256, GEMM_SMEM_BYTES>>>(pth, pWth + 0 * WSZ, px, pxrh);

    // 3 fused GCN layers, ping-pong buffers (inputs never written in-kernel)
    gcn_fused<1><<<gg, 256, FUSED_SMEM_BYTES>>>(pxrh,  px,  px2, pxrh2, pWth + 1 * WSZ, bg1);
    gcn_fused<1><<<gg, 256, FUSED_SMEM_BYTES>>>(pxrh2, px2, px,  pxrh,  pWth + 2 * WSZ, bg2);
    gcn_fused<0><<<gg, 256, FUSED_SMEM_BYTES>>>(pxrh,  px,  px2, nullptr, pWth + 3 * WSZ, bg3);

    head_kernel<<<Bn, 256>>>(px2, fcW, fcb, gspan, out);
}

// round 17
// speedup vs baseline: 1.4842x; 1.0228x over previous
#include <cuda_runtime.h>
#include <cuda_fp16.h>
#include <cstdint>

// Problem constants
#define Bn 64
#define Sn 512
#define Nn 128
#define Dn 768
#define On 3

// Scratch (device globals -- no allocations allowed)
__device__ float  g_x[(size_t)Bn * Nn * Dn];     // exact node features (ping)
__device__ float  g_x2[(size_t)Bn * Nn * Dn];    // exact node features (pong)
__device__ __half g_xrh[(size_t)Bn * Nn * Dn];   // fp16, K-permuted (ping)
__device__ __half g_xrh2[(size_t)Bn * Nn * Dn];  // fp16, K-permuted (pong)
__device__ __half g_th[(size_t)Bn * Nn * Dn];    // span sums, fp16 permuted
__device__ __half g_adjh[(size_t)Bn * Nn * Nn];  // adjacency fp16 (0/1 exact), permuted
__device__ float  g_denom[(size_t)Bn * Nn];      // row-degree + 1e-7
__device__ float  g_tmax[(size_t)Bn * Dn];       // target max-pool
__device__ __half g_Wth[4 * (size_t)Dn * Dn];    // W^T [N,K] fp16, K-permuted

// ===========================================================================
// helpers
// ===========================================================================
__device__ __forceinline__ uint32_t smem_u32(const void* p) {
    uint32_t a;
    asm("{ .reg .u64 t; cvta.to.shared.u64 t, %1; cvt.u32.u64 %0, t; }" : "=r"(a) : "l"(p));
    return a;
}
// fp16 k16 fragment permutation within each 16-group:
// logical k = 2t+d+8e (t=0..3,d=0..1,e=0..1) -> phys 4t+2e+d
__device__ __forceinline__ int phys16(int j) {
    return (((j & 7) >> 1) << 2) | (((j >> 3) & 1) << 1) | (j & 1);
}
__device__ __forceinline__ int permh(int k) {
    return (k & ~15) | phys16(k & 15);
}
#define CP_ASYNC16(dst, src) \
    asm volatile("cp.async.cg.shared.global [%0], [%1], 16;" :: "r"(dst), "l"(src) : "memory")
#define CP_COMMIT() asm volatile("cp.async.commit_group;" ::: "memory")
#define CP_WAIT(n)  asm volatile("cp.async.wait_group %0;" :: "n"(n) : "memory")

__device__ __forceinline__ void mma_f16(float& c0, float& c1, float& c2, float& c3,
                                        uint32_t a0, uint32_t a1, uint32_t a2, uint32_t a3,
                                        uint32_t b0, uint32_t b1) {
    asm volatile(
        "mma.sync.aligned.m16n8k16.row.col.f32.f16.f16.f32 "
        "{%0,%1,%2,%3}, {%4,%5,%6,%7}, {%8,%9}, {%0,%1,%2,%3};"
        : "+f"(c0), "+f"(c1), "+f"(c2), "+f"(c3)
        : "r"(a0), "r"(a1), "r"(a2), "r"(a3), "r"(b0), "r"(b1));
}

// ===========================================================================
// MERGED prep kernel (unchanged from R16)
// ===========================================================================
#define PREP_ADJ_BLKS   4096
#define PREP_SPAN_BLKS  8192
#define PREP_TMAX_BLKS  64
#define PREP_WT_BLKS    2304
#define PREP_GRID (PREP_ADJ_BLKS + PREP_SPAN_BLKS + PREP_TMAX_BLKS + PREP_WT_BLKS)

__global__ void prep_kernel(const float* __restrict__ se,
                            const float* __restrict__ dg, const float* __restrict__ dg1,
                            const float* __restrict__ W0, const float* __restrict__ W1,
                            const float* __restrict__ W2, const float* __restrict__ W3,
                            const int* __restrict__ tspan, const int* __restrict__ tran) {
    int blk = blockIdx.x;
    int tid = threadIdx.x;

    if (blk < PREP_ADJ_BLKS) {
        int row = blk * 2 + (tid >> 7);
        int col = tid & 127;
        float a = dg[(size_t)row * Nn + col] + dg1[(size_t)row * Nn + col];
        a = fminf(a, 1.0f);
        g_adjh[(size_t)row * Nn + permh(col)] = __float2half_rn(a);
        __shared__ float s[256];
        s[tid] = a;
        __syncthreads();
        #pragma unroll
        for (int st = 64; st > 0; st >>= 1) {
            if ((tid & 127) < st) s[tid] += s[tid + st];
            __syncthreads();
        }
        if ((tid & 127) == 0) g_denom[row] = s[tid] + 1e-7f;
    } else if (blk < PREP_ADJ_BLKS + PREP_SPAN_BLKS) {
        int row = blk - PREP_ADJ_BLKS;
        int b = row >> 7;
        int s0 = tran[row * 2] + 1;
        int e0 = tran[row * 2 + 1] + 1;
        for (int d = tid; d < Dn; d += 256) {
            float acc = 0.0f;
            for (int s = s0; s < e0; ++s)
                acc += se[((size_t)b * Sn + s) * Dn + d];
            g_th[(size_t)row * Dn + permh(d)] = __float2half_rn(acc);
        }
    } else if (blk < PREP_ADJ_BLKS + PREP_SPAN_BLKS + PREP_TMAX_BLKS) {
        int b = blk - (PREP_ADJ_BLKS + PREP_SPAN_BLKS);
        int l = tspan[b * 2];
        int r = tspan[b * 2 + 1];
        for (int d = tid; d < Dn; d += 256) {
            float m = -3.402823466e38f;
            for (int s = l; s < r; ++s)
                m = fmaxf(m, se[((size_t)b * Sn + s) * Dn + d]);
            g_tmax[(size_t)b * Dn + d] = m;
        }
    } else {
        int idx = blk - (PREP_ADJ_BLKS + PREP_SPAN_BLKS + PREP_TMAX_BLKS);
        int w = idx / 576;
        int rem = idx % 576;
        int by = rem / 24;
        int bx = rem % 24;
        int tx = tid & 31;
        int ty = tid >> 5;
        __shared__ float t[32][33];
        const float* W = (w == 0) ? W0 : (w == 1) ? W1 : (w == 2) ? W2 : W3;
        __half* O = g_Wth + (size_t)w * Dn * Dn;
        int nx = bx * 32;
        int ky = by * 32;
        for (int i = ty; i < 32; i += 8)
            t[i][tx] = W[(size_t)(ky + i) * Dn + nx + tx];
        __syncthreads();
        for (int i = ty; i < 32; i += 8)
            O[(size_t)(nx + i) * Dn + permh(ky + tx)] = __float2half_rn(t[tx][i]);
    }
}

// ===========================================================================
// fp16 tile geometry: 128(M) x 96(N), BK=32 halves, dense 64B rows +
// XOR-16B-chunk swizzle (chunk' = chunk ^ (row & 3)) -- conflict-free for
// both cp.async 16B stores and uint2 fragment loads. NST=4 pipeline.
// ===========================================================================
#define BKH 32
#define BN 96
#define A_TILE_H (128 * 32)               // 4096 halves (8KB)
#define B_TILE_H (BN * 32)                // 3072 halves (6KB)
#define STAGE_H (A_TILE_H + B_TILE_H)     // 7168 halves (14KB)
#define NST 4
#define REGION0_H (NST * STAGE_H)         // 28672 halves (57344 B)
#define PT_CHUNK_H B_TILE_H               // 3072 halves per node-k chunk
#define GEMM_SMEM_BYTES (REGION0_H * 2)                      // 57344
#define FUSED_SMEM_BYTES ((REGION0_H + NST * A_TILE_H) * 2)  // 90112

// swizzled half-offset of fragment (row, kstep s, thread group tg)
#define FRAG_OFF(r, s) \
    ((r) * 32 + ((((((s) << 1) + (tg >> 1))) ^ ((r) & 3)) << 3) + ((tg & 1) << 2))

// per-k32-tile MMA body: 2 fp16 k16-steps; warp tile 32x48
#define MMA_TILE_BODY(ash, bsh)                                                         \
    do {                                                                                \
        _Pragma("unroll")                                                               \
        for (int s = 0; s < 2; ++s) {                                                   \
            uint2 ar0[2], ar1[2], bv[6];                                                \
            _Pragma("unroll")                                                           \
            for (int mi = 0; mi < 2; ++mi) {                                            \
                ar0[mi] = *(const uint2*)&(ash)[FRAG_OFF(wm + mi * 16 + lg, s)];        \
                ar1[mi] = *(const uint2*)&(ash)[FRAG_OFF(wm + mi * 16 + lg + 8, s)];    \
            }                                                                           \
            _Pragma("unroll")                                                           \
            for (int ni = 0; ni < 6; ++ni)                                              \
                bv[ni] = *(const uint2*)&(bsh)[FRAG_OFF(wn + ni * 8 + lg, s)];          \
            _Pragma("unroll")                                                           \
            for (int mi = 0; mi < 2; ++mi)                                              \
                _Pragma("unroll")                                                       \
                for (int ni = 0; ni < 6; ++ni)                                          \
                    mma_f16(c[mi][ni][0], c[mi][ni][1], c[mi][ni][2], c[mi][ni][3],     \
                            ar0[mi].x, ar1[mi].x, ar0[mi].y, ar1[mi].y,                 \
                            bv[ni].x, bv[ni].y);                                        \
        }                                                                               \
    } while (0)

// loaders (256 threads); 64B/row dense, 16B chunks XOR-swizzled by row&3
#define LOAD_A_TILE(sbase, ptr, ld, k0)                                                \
    do {                                                                               \
        _Pragma("unroll")                                                              \
        for (int i = 0; i < 2; ++i) {                                                  \
            int id = tid + i * 256;                                                    \
            int row = id >> 2;                                                         \
            int seg = id & 3;                                                          \
            CP_ASYNC16((sbase) + row * 64 + (((seg) ^ (row & 3)) << 4),                \
                       (ptr) + (size_t)row * (ld) + (k0) + seg * 8);                   \
        }                                                                              \
    } while (0)

#define LOAD_B_TILE(sbase, ptr, ld, k0)                                                \
    do {                                                                               \
        int row = tid >> 2;                                                            \
        int seg = tid & 3;                                                             \
        CP_ASYNC16((sbase) + row * 64 + (((seg) ^ (row & 3)) << 4),                    \
                   (ptr) + (size_t)row * (ld) + (k0) + seg * 8);                       \
        if (tid < 128) {                                                               \
            int id2 = tid + 256;                                                       \
            int row2 = id2 >> 2;                                                       \
            int seg2 = id2 & 3;                                                        \
            CP_ASYNC16((sbase) + row2 * 64 + (((seg2) ^ (row2 & 3)) << 4),             \
                       (ptr) + (size_t)row2 * (ld) + (k0) + seg2 * 8);                 \
        }                                                                              \
    } while (0)

// ===========================================================================
// projection GEMM: Xout = relu(g_th @ Wproj^T); XRout = fp16 permuted copy
// ===========================================================================
template <int KTILES>
__global__ void __launch_bounds__(256, 2)
gemm_proj(const __half* __restrict__ A, const __half* __restrict__ B,
          float* __restrict__ Xout, __half* __restrict__ XRout) {
    extern __shared__ __half smh[];
    int tid = threadIdx.x;
    int lane = tid & 31;
    int warp = tid >> 5;
    int wm = (warp >> 1) * 32;
    int wn = (warp & 1) * 48;
    int lg = lane >> 2;
    int tg = lane & 3;

    const __half* Ab = A + (size_t)blockIdx.y * 128 * Dn;
    const __half* Bb = B + (size_t)blockIdx.x * BN * Dn;

    float c[2][6][4];
    #pragma unroll
    for (int i = 0; i < 2; ++i)
        #pragma unroll
        for (int j = 0; j < 6; ++j)
            #pragma unroll
            for (int k = 0; k < 4; ++k) c[i][j][k] = 0.0f;

    uint32_t sAb[NST], sBb[NST];
    #pragma unroll
    for (int s = 0; s < NST; ++s) {
        sAb[s] = smem_u32(smh + s * STAGE_H);
        sBb[s] = smem_u32(smh + s * STAGE_H + A_TILE_H);
    }

    auto load_stage = [&](int it, int buf) {
        int k0 = it * BKH;
        LOAD_A_TILE(sAb[buf], Ab, Dn, k0);
        LOAD_B_TILE(sBb[buf], Bb, Dn, k0);
        CP_COMMIT();
    };

    load_stage(0, 0);
    load_stage(1, 1);
    load_stage(2, 2);
    for (int it = 0; it < KTILES; ++it) {
        int buf = it & (NST - 1);
        if (it == KTILES - 1) { CP_WAIT(0); } else { CP_WAIT(2); }
        __syncthreads();
        if (it + 3 < KTILES) load_stage(it + 3, (it + 3) & (NST - 1));

        const __half* ash = smh + buf * STAGE_H;
        const __half* bsh = smh + buf * STAGE_H + A_TILE_H;
        MMA_TILE_BODY(ash, bsh);
    }

    size_t row0 = (size_t)blockIdx.y * 128;
    #pragma unroll
    for (int mi = 0; mi < 2; ++mi) {
        int r = wm + mi * 16 + lg;
        #pragma unroll
        for (int ni = 0; ni < 6; ++ni) {
            int cc = blockIdx.x * BN + wn + ni * 8 + 2 * tg;
            float v0 = fmaxf(c[mi][ni][0], 0.0f);
            float v1 = fmaxf(c[mi][ni][1], 0.0f);
            float v2 = fmaxf(c[mi][ni][2], 0.0f);
            float v3 = fmaxf(c[mi][ni][3], 0.0f);
            Xout[(row0 + r) * Dn + cc]          = v0;
            Xout[(row0 + r) * Dn + cc + 1]      = v1;
            Xout[(row0 + r + 8) * Dn + cc]      = v2;
            Xout[(row0 + r + 8) * Dn + cc + 1]  = v3;
            XRout[(row0 + r) * Dn + permh(cc)]         = __float2half_rn(v0);
            XRout[(row0 + r) * Dn + permh(cc + 1)]     = __float2half_rn(v1);
            XRout[(row0 + r + 8) * Dn + permh(cc)]     = __float2half_rn(v2);
            XRout[(row0 + r + 8) * Dn + permh(cc + 1)] = __float2half_rn(v3);
        }
    }
}

// ===========================================================================
// FUSED GCN layer (ping-pong, race-free): per (dtile=blockIdx.x, b=blockIdx.y)
// ===========================================================================
template <int WXR>
__global__ void __launch_bounds__(256, 2)
gcn_fused(const __half* __restrict__ XRin, const float* __restrict__ Xin,
          float* __restrict__ Xout, __half* __restrict__ XRout,
          const __half* __restrict__ B, const float* __restrict__ bias) {
    extern __shared__ __half smh[];
    int tid = threadIdx.x;
    int lane = tid & 31;
    int warp = tid >> 5;
    int wm = (warp >> 1) * 32;
    int wn = (warp & 1) * 48;
    int lg = lane >> 2;
    int tg = lane & 3;

    int b = blockIdx.y;
    const __half* Ab = XRin + (size_t)b * 128 * Dn;
    const __half* Bb = B + (size_t)blockIdx.x * BN * Dn;

    float c[2][6][4];
    #pragma unroll
    for (int i = 0; i < 2; ++i)
        #pragma unroll
        for (int j = 0; j < 6; ++j)
            #pragma unroll
            for (int k = 0; k < 4; ++k) c[i][j][k] = 0.0f;

    uint32_t sAb[NST], sBb[NST], sAdj[NST];
    #pragma unroll
    for (int s = 0; s < NST; ++s) {
        sAb[s]  = smem_u32(smh + s * STAGE_H);
        sBb[s]  = smem_u32(smh + s * STAGE_H + A_TILE_H);
        sAdj[s] = smem_u32(smh + REGION0_H + s * A_TILE_H);
    }

    // ---- phase 1: P = XRin[b] @ W^T ----
    auto load_stage = [&](int it, int buf) {
        int k0 = it * BKH;
        LOAD_A_TILE(sAb[buf], Ab, Dn, k0);
        LOAD_B_TILE(sBb[buf], Bb, Dn, k0);
        CP_COMMIT();
    };

    load_stage(0, 0);
    load_stage(1, 1);
    load_stage(2, 2);
    const int KT1 = Dn / BKH;   // 24
    for (int it = 0; it < KT1; ++it) {
        int buf = it & (NST - 1);
        if (it == KT1 - 1) { CP_WAIT(0); } else { CP_WAIT(2); }
        __syncthreads();
        if (it + 3 < KT1) load_stage(it + 3, (it + 3) & (NST - 1));

        const __half* ash = smh + buf * STAGE_H;
        const __half* bsh = smh + buf * STAGE_H + A_TILE_H;
        MMA_TILE_BODY(ash, bsh);
    }
    __syncthreads();

    // ---- stage P^T into region0: 4 node-k chunks [96 d-rows][32 swizzled] ----
    // node m -> chunk m>>5, within-chunk phys p = (m&16)|phys16(m&15);
    // stored at d-row dl: dl*32 + ((p>>3)^(dl&3))*8 + (p&7)
    #pragma unroll
    for (int mi = 0; mi < 2; ++mi) {
        int m0 = wm + mi * 16 + lg;
        int m1 = m0 + 8;
        int cb0 = (m0 >> 5) * PT_CHUNK_H;
        int cb1 = (m1 >> 5) * PT_CHUNK_H;
        int p0 = (m0 & 16) | phys16(m0 & 15);
        int p1 = (m1 & 16) | phys16(m1 & 15);
        #pragma unroll
        for (int ni = 0; ni < 6; ++ni) {
            int dl = wn + ni * 8 + 2 * tg;
            int d2 = dl + 1;
            smh[cb0 + dl * 32 + ((((p0 >> 3) ^ (dl & 3))) << 3) + (p0 & 7)] = __float2half_rn(c[mi][ni][0]);
            smh[cb0 + d2 * 32 + ((((p0 >> 3) ^ (d2 & 3))) << 3) + (p0 & 7)] = __float2half_rn(c[mi][ni][1]);
            smh[cb1 + dl * 32 + ((((p1 >> 3) ^ (dl & 3))) << 3) + (p1 & 7)] = __float2half_rn(c[mi][ni][2]);
            smh[cb1 + d2 * 32 + ((((p1 >> 3) ^ (d2 & 3))) << 3) + (p1 & 7)] = __float2half_rn(c[mi][ni][3]);
            c[mi][ni][0] = 0.0f; c[mi][ni][1] = 0.0f;
            c[mi][ni][2] = 0.0f; c[mi][ni][3] = 0.0f;
        }
    }
    __syncthreads();

    // ---- phase 2: acc = adjh[b] @ P  (K = 128 nodes, 4 k32-tiles) ----
    const __half* adjb = g_adjh + (size_t)b * Nn * Nn;
    auto load_adj = [&](int it, int buf) {
        int k0 = it * BKH;
        LOAD_A_TILE(sAdj[buf], adjb, Nn, k0);
        CP_COMMIT();
    };

    load_adj(0, 0);
    load_adj(1, 1);
    load_adj(2, 2);
    for (int it = 0; it < 4; ++it) {
        int buf = it & (NST - 1);
        if (it == 3) { CP_WAIT(0); } else { CP_WAIT(2); }
        __syncthreads();
        if (it + 3 < 4) load_adj(it + 3, (it + 3) & (NST - 1));

        const __half* ash = smh + REGION0_H + buf * A_TILE_H;
        const __half* bsh = smh + it * PT_CHUNK_H;
        MMA_TILE_BODY(ash, bsh);
    }

    // ---- epilogue: residual + relu + bias ----
    #pragma unroll
    for (int mi = 0; mi < 2; ++mi) {
        int r = wm + mi * 16 + lg;
        float id0 = 1.0f / g_denom[b * Nn + r];
        float id1 = 1.0f / g_denom[b * Nn + r + 8];
        size_t row0 = (size_t)(b * Nn + r);
        size_t row1 = row0 + 8;
        #pragma unroll
        for (int ni = 0; ni < 6; ++ni) {
            int cc = blockIdx.x * BN + wn + ni * 8 + 2 * tg;
            float n0 = Xin[row0 * Dn + cc]     + fmaxf(c[mi][ni][0] * id0 + bias[cc], 0.0f);
            float n1 = Xin[row0 * Dn + cc + 1] + fmaxf(c[mi][ni][1] * id0 + bias[cc + 1], 0.0f);
            float n2 = Xin[row1 * Dn + cc]     + fmaxf(c[mi][ni][2] * id1 + bias[cc], 0.0f);
            float n3 = Xin[row1 * Dn + cc + 1] + fmaxf(c[mi][ni][3] * id1 + bias[cc + 1], 0.0f);
            Xout[row0 * Dn + cc]     = n0;
            Xout[row0 * Dn + cc + 1] = n1;
            Xout[row1 * Dn + cc]     = n2;
            Xout[row1 * Dn + cc + 1] = n3;
            if (WXR) {
                XRout[row0 * Dn + permh(cc)]     = __float2half_rn(n0);
                XRout[row0 * Dn + permh(cc + 1)] = __float2half_rn(n1);
                XRout[row1 * Dn + permh(cc)]     = __float2half_rn(n2);
                XRout[row1 * Dn + permh(cc + 1)] = __float2half_rn(n3);
            }
        }
    }
}

// ===========================================================================
// head: gcn_target (node-span sum) + concat + fc + tanh (reads Xfinal)
// ===========================================================================
__global__ void head_kernel(const float* __restrict__ Xfinal,
                            const float* __restrict__ fcW, const float* __restrict__ fcb,
                            const int* __restrict__ gspan, float* __restrict__ out) {
    int b = blockIdx.x;
    int tid = threadIdx.x;
    int gs = gspan[b * 2];
    int ge = gspan[b * 2 + 1];
    float p0 = 0.0f, p1 = 0.0f, p2 = 0.0f;
    for (int d = tid; d < Dn; d += 256) {
        float tm = g_tmax[(size_t)b * Dn + d];
        float gt = 0.0f;
        for (int n = gs; n < ge; ++n)
            gt += Xfinal[((size_t)b * Nn + n) * Dn + d];
        p0 += tm * fcW[d * On + 0] + gt * fcW[(Dn + d) * On + 0];
        p1 += tm * fcW[d * On + 1] + gt * fcW[(Dn + d) * On + 1];
        p2 += tm * fcW[d * On + 2] + gt * fcW[(Dn + d) * On + 2];
    }
    __shared__ float r0[256], r1[256], r2[256];
    r0[tid] = p0; r1[tid] = p1; r2[tid] = p2;
    __syncthreads();
    #pragma unroll
    for (int st = 128; st > 0; st >>= 1) {
        if (tid < st) { r0[tid] += r0[tid + st]; r1[tid] += r1[tid + st]; r2[tid] += r2[tid + st]; }
        __syncthreads();
    }
    if (tid == 0) {
        out[b * On + 0] = tanhf(r0[0] + fcb[0]);
        out[b * On + 1] = tanhf(r1[0] + fcb[1]);
        out[b * On + 2] = tanhf(r2[0] + fcb[2]);
    }
}

// ===========================================================================
extern "C" void kernel_launch(void* const* d_in, const int* in_sizes, int n_in,
                              void* d_out, int out_size) {
    const float* se    = (const float*)d_in[0];
    const float* dg    = (const float*)d_in[1];
    const float* dg1   = (const float*)d_in[2];
    const float* Wproj = (const float*)d_in[3];
    const float* Wg1   = (const float*)d_in[4];
    const float* bg1   = (const float*)d_in[5];
    const float* Wg2   = (const float*)d_in[6];
    const float* bg2   = (const float*)d_in[7];
    const float* Wg3   = (const float*)d_in[8];
    const float* bg3   = (const float*)d_in[9];
    const float* fcW   = (const float*)d_in[10];
    const float* fcb   = (const float*)d_in[11];
    const int*   tspan = (const int*)d_in[12];
    const int*   tran  = (const int*)d_in[13];
    const int*   gspan = (const int*)d_in[14];
    float* out = (float*)d_out;

    float *px, *px2;
    __half *pth, *pxrh, *pxrh2, *pWth;
    cudaGetSymbolAddress((void**)&px, g_x);
    cudaGetSymbolAddress((void**)&px2, g_x2);
    cudaGetSymbolAddress((void**)&pth, g_th);
    cudaGetSymbolAddress((void**)&pxrh, g_xrh);
    cudaGetSymbolAddress((void**)&pxrh2, g_xrh2);
    cudaGetSymbolAddress((void**)&pWth, g_Wth);

    cudaFuncSetAttribute(gemm_proj<24>, cudaFuncAttributeMaxDynamicSharedMemorySize, GEMM_SMEM_BYTES);
    cudaFuncSetAttribute(gcn_fused<1>, cudaFuncAttributeMaxDynamicSharedMemorySize, FUSED_SMEM_BYTES);
    cudaFuncSetAttribute(gcn_fused<0>, cudaFuncAttributeMaxDynamicSharedMemorySize, FUSED_SMEM_BYTES);

    dim3 gg(Dn / BN, 64);   // (8, 64) = 512 tiles

    // merged prep: adj + span + tmax + wtrans overlapped in one launch
    prep_kernel<<<PREP_GRID, 256>>>(se, dg, dg1, Wproj, Wg1, Wg2, Wg3, tspan, tran);

    const size_t WSZ = (size_t)Dn * Dn;

    // x = relu(tmps @ W_proj)  -> (g_x, g_xrh)
    gemm_proj<24><<<gg, 256, GEMM_SMEM_BYTES>>>(pth, pWth + 0 * WSZ, px, pxrh);

    // 3 fused GCN layers, ping-pong buffers (inputs never written in-kernel)
    gcn_fused<1><<<gg, 256, FUSED_SMEM_BYTES>>>(pxrh,  px,  px2, pxrh2, pWth + 1 * WSZ, bg1);
    gcn_fused<1><<<gg, 256, FUSED_SMEM_BYTES>>>(pxrh2, px2, px,  pxrh,  pWth + 2 * WSZ, bg2);
    gcn_fused<0><<<gg, 256, FUSED_SMEM_BYTES>>>(pxrh,  px,  px2, nullptr, pWth + 3 * WSZ, bg3);

    head_kernel<<<Bn, 256>>>(px2, fcW, fcb, gspan, out);
}